// round 8
// baseline (speedup 1.0000x reference)
#include <cuda_runtime.h>
#include <math.h>

// ---------------------------------------------------------------------------
// Problem constants
// ---------------------------------------------------------------------------
#define BETA      10.0
#define LTAU      1000
#define N_NODES   256
#define N_IWN     256
#define BATCH     16
#define N_POLES   16

#define STEP_D    (9.99 / 999.0)            // linspace(0, BETA-DTAU, LTAU) step
#define LOG2E_F   1.4426950408889634f
#define PI_D      3.141592653589793
#define ZETA3     1.2020569031595942
#define ZETA5     1.0369277551433699

// Gauss-Legendre tables, computed on HOST (deterministic double Newton) each
// call and passed BY VALUE as kernel parameters -> baked into the graph node.
struct GLTab {
    float phi[N_NODES];
    float wgt[N_NODES];
};

// Per-(b,p,node-quarter) partial G_tau.  1024 * 1000 floats = 4 MB (static).
__device__ float g_partial4[BATCH * N_POLES * 4 * LTAU];

__device__ __forceinline__ float fexp2(float x) {
    float y;
    asm("ex2.approx.ftz.f32 %0, %1;" : "=f"(y) : "f"(x));
    return y;
}

// ---- packed f32x2 helpers (Blackwell FFMA2 path, PTX-only) ----------------
__device__ __forceinline__ unsigned long long pk2(float lo, float hi) {
    unsigned long long r;
    asm("mov.b64 %0, {%1, %2};" : "=l"(r) : "f"(lo), "f"(hi));
    return r;
}
__device__ __forceinline__ void unpk2(float& lo, float& hi, unsigned long long v) {
    asm("mov.b64 {%0, %1}, %2;" : "=f"(lo), "=f"(hi) : "l"(v));
}
__device__ __forceinline__ unsigned long long fma2(unsigned long long a,
                                                   unsigned long long b,
                                                   unsigned long long c) {
    unsigned long long d;
    asm("fma.rn.f32x2 %0, %1, %2, %3;" : "=l"(d) : "l"(a), "l"(b), "l"(c));
    return d;
}
__device__ __forceinline__ unsigned long long mul2(unsigned long long a,
                                                   unsigned long long b) {
    unsigned long long d;
    asm("mul.rn.f32x2 %0, %1, %2;" : "=l"(d) : "l"(a), "l"(b));
    return d;
}

// ---------------------------------------------------------------------------
// Quadrature kernel.  Block = (bp, node-quarter q); 128 threads.
// Threads 0..63 precompute the factored Fermi form (one node each, writing
// straight into the packed node-pair layout); threads 0..124 then each cover
// 8 consecutive taus via a geometric recurrence, node pairs in f32x2 lanes:
//   term(n,l) = pg * 2^( q2*tau_l + d2 ),   e_{l+1} = e_l * rho
//   q2 = -omega*log2e,  d2 = BETA*min(omega,0)*log2e
//   pg = 0.5*(a - b*phi) * w / (1 + exp(-BETA*|omega|))
// fma-pipe cost: ~0.94 f32x2-ops per (node,tau); 1 EX2 per node per 8 taus.
// ---------------------------------------------------------------------------
__global__ void __launch_bounds__(128) quad_kernel(
    const GLTab tab,
    const float* __restrict__ pre, const float* __restrict__ pim,
    const float* __restrict__ rre, const float* __restrict__ rim)
{
    __shared__ float4     sh_qd[32];   // {q2_a, d2_a, q2_b, d2_b} per pair
    __shared__ ulonglong2 sh_pr[32];   // {pg packed, rho packed}  per pair
    const int bp = blockIdx.x >> 2;    // b*16 + p
    const int q  = blockIdx.x & 3;     // node quarter
    const int t  = threadIdx.x;

    if (t < 64) {                      // per-node precompute (1 node / thread)
        const int n = q * 64 + t;
        float eps = pre[bp];
        float gam = -pim[bp];
        float a   = rre[bp];
        float br  = rim[bp];
        float phi = tab.phi[n];
        float wq  = tab.wgt[n];

        float omega = fmaf(gam, phi, eps);
        float s     = fabsf(omega);
        float q2 = -omega * LOG2E_F;
        float d2 = 10.0f * fminf(omega, 0.0f) * LOG2E_F;
        float gfac = 1.0f / (1.0f + fexp2(-10.0f * LOG2E_F * s));
        float pg = 0.5f * fmaf(-br, phi, a) * wq * gfac;
        // clamp keeps rho finite; when active, the thread's starting
        // exponential has already flushed to 0 -> no corruption possible
        float rho = fexp2(fminf(q2 * (float)STEP_D, 80.0f));

        const int p = t >> 1, k = t & 1;       // pair index / half
        float* qd = (float*)&sh_qd[p];
        qd[2 * k]     = q2;
        qd[2 * k + 1] = d2;
        float* pr = (float*)&sh_pr[p];
        pr[k]     = pg;                        // pg packed lo/hi
        pr[2 + k] = rho;                       // rho packed lo/hi
    }
    __syncthreads();

    if (t >= 125) return;              // 125 threads * 8 taus = 1000
    const int l0 = 8 * t;
    const float tau0 = (float)((double)l0 * STEP_D);

    unsigned long long A0 = 0, A1 = 0, A2 = 0, A3 = 0,
                       A4 = 0, A5 = 0, A6 = 0, A7 = 0;
    #pragma unroll 4
    for (int p = 0; p < 32; ++p) {
        float4     qd = sh_qd[p];       // broadcast LDS.128
        ulonglong2 pr = sh_pr[p];       // broadcast LDS.128
        float e0 = fexp2(fmaf(qd.x, tau0, qd.y));
        float e1 = fexp2(fmaf(qd.z, tau0, qd.w));
        unsigned long long E = pk2(e0, e1);
        A0 = fma2(pr.x, E, A0);  E = mul2(E, pr.y);
        A1 = fma2(pr.x, E, A1);  E = mul2(E, pr.y);
        A2 = fma2(pr.x, E, A2);  E = mul2(E, pr.y);
        A3 = fma2(pr.x, E, A3);  E = mul2(E, pr.y);
        A4 = fma2(pr.x, E, A4);  E = mul2(E, pr.y);
        A5 = fma2(pr.x, E, A5);  E = mul2(E, pr.y);
        A6 = fma2(pr.x, E, A6);  E = mul2(E, pr.y);
        A7 = fma2(pr.x, E, A7);
    }

    float lo, hi, r0, r1, r2, r3, r4, r5, r6, r7;
    unpk2(lo, hi, A0); r0 = lo + hi;
    unpk2(lo, hi, A1); r1 = lo + hi;
    unpk2(lo, hi, A2); r2 = lo + hi;
    unpk2(lo, hi, A3); r3 = lo + hi;
    unpk2(lo, hi, A4); r4 = lo + hi;
    unpk2(lo, hi, A5); r5 = lo + hi;
    unpk2(lo, hi, A6); r6 = lo + hi;
    unpk2(lo, hi, A7); r7 = lo + hi;

    float4* dst = (float4*)&g_partial4[(size_t)blockIdx.x * LTAU];
    dst[2 * t]     = make_float4(r0, r1, r2, r3);
    dst[2 * t + 1] = make_float4(r4, r5, r6, r7);
}

// ---------------------------------------------------------------------------
// Fused reduce + G0 kernel (grid = 64 + 16 blocks, 256 threads).
//  Blocks 0..63 : sum the 64 (pole x quarter) chunks for every tau >= 1.
//    block = (b, tau-block tb of 64 float4-groups);  thread = (c4 = t>>6
//    chunk-quarter, g = t&63 float4-group).  Lanes of a warp walk consecutive
//    float4s of the SAME chunk -> perfectly coalesced LDG.128, 16 independent
//    loads per thread (full MLP).  Chunk-quarters combined via shared memory.
//  Blocks 64..79: Matsubara tail -> out[b][0]   (independent of the above)
//   Re(res/(z-i*nu)) = (a*eps - b*(gam+nu)) / (eps^2 + (gam+nu)^2)
//   Re(c1)/iwn correction is purely imaginary -> drops
//   corrections: +Re(c2)/nu^2 + Im(c3)/nu^3 - Re(c4)/nu^4 - Im(c5)/nu^5
// ---------------------------------------------------------------------------
__global__ void __launch_bounds__(256) reduce_g0_kernel(
    const float* __restrict__ pre, const float* __restrict__ pim,
    const float* __restrict__ rre, const float* __restrict__ rim,
    float* __restrict__ out)
{
    const int t = threadIdx.x;

    if (blockIdx.x < 64) {
        __shared__ float4 sh[4][64];
        const int b  = blockIdx.x >> 2;      // batch
        const int tb = blockIdx.x & 3;       // tau-block (64 float4-groups)
        const int c4 = t >> 6;               // chunk quarter 0..3
        const int g  = t & 63;               // float4-group within tau-block
        const int gg = tb * 64 + g;          // global float4-group 0..255

        float4 s = make_float4(0.f, 0.f, 0.f, 0.f);
        if (gg < 250) {
            const float4* src = (const float4*)g_partial4
                              + ((size_t)(b * 64 + c4 * 16)) * 250 + gg;
            #pragma unroll
            for (int k = 0; k < 16; ++k) {   // 16 independent coalesced loads
                float4 v = src[(size_t)k * 250];
                s.x += v.x; s.y += v.y; s.z += v.z; s.w += v.w;
            }
        }
        sh[c4][g] = s;
        __syncthreads();

        if (t < 64) {                        // c4==0 lanes finalize
            const int gg2 = tb * 64 + t;
            if (gg2 < 250) {
                float4 v0 = sh[0][t], v1 = sh[1][t], v2 = sh[2][t], v3 = sh[3][t];
                float4 r;
                r.x = (v0.x + v1.x) + (v2.x + v3.x);
                r.y = (v0.y + v1.y) + (v2.y + v3.y);
                r.z = (v0.z + v1.z) + (v2.z + v3.z);
                r.w = (v0.w + v1.w) + (v2.w + v3.w);
                float* dst = out + (size_t)b * LTAU + 4 * gg2;
                if (gg2 == 0) { dst[1] = r.y; dst[2] = r.z; dst[3] = r.w; }
                else          { *(float4*)dst = r; }
            }
        }
        return;
    }

    // ---- G0 (Matsubara tail), thread t = frequency t ----
    __shared__ double red[256];
    const int b = blockIdx.x - 64;
    const float nu = (2.0f * (float)t + 1.0f) * (float)(PI_D / 10.0);
    float Ff = 0.f, s1 = 0.f, s2 = 0.f, s3 = 0.f, s4 = 0.f, s5 = 0.f;

    #pragma unroll
    for (int p = 0; p < N_POLES; ++p) {
        float eps = pre[b * N_POLES + p];
        float gam = -pim[b * N_POLES + p];
        float a   = rre[b * N_POLES + p];
        float bb  = rim[b * N_POLES + p];

        float D = gam + nu;
        Ff += (a * eps - bb * D) / fmaf(eps, eps, D * D);

        // c-chain: c1 = -res ; c_{k+1} = c_k * z, z = eps - i*gam
        float zr = eps, zi = -gam;
        float cr = -a, ci = -bb;
        s1 += cr;
        float r2 = cr * zr - ci * zi, i2 = cr * zi + ci * zr;  s2 += r2;
        float r3 = r2 * zr - i2 * zi, i3 = r2 * zi + i2 * zr;  s3 += i3;
        float r4 = r3 * zr - i3 * zi, i4 = r3 * zi + i3 * zr;  s4 += r4;
        float r5 = r4 * zr - i4 * zi, i5 = r4 * zi + i4 * zr;  s5 += i5;
    }
    float nu2 = nu * nu;
    float nu3 = nu2 * nu;
    Ff += s2 / nu2 + s3 / nu3 - s4 / (nu2 * nu2) - s5 / (nu2 * nu3);

    red[t] = (double)Ff;
    __syncthreads();
    for (int off = 128; off > 0; off >>= 1) {
        if (t < off) red[t] += red[t + off];
        __syncthreads();
    }

    if (t == 0) {
        const double C0 = -0.5;
        const double C1 = -BETA / 4.0;
        const double C2 = -7.0 * ZETA3 * BETA * BETA / (4.0 * PI_D * PI_D * PI_D);
        const double C3 = BETA * BETA * BETA / 48.0;
        const double C4 = 31.0 * ZETA5 * BETA * BETA * BETA * BETA /
                          (16.0 * PI_D * PI_D * PI_D * PI_D * PI_D);
        double G0 = C0 * (double)s1 + C1 * (double)s2 + C2 * (double)s3 +
                    C3 * (double)s4 + C4 * (double)s5 +
                    2.0 * red[0] / BETA;
        out[(size_t)b * LTAU] = (float)G0;
    }
}

// ---------------------------------------------------------------------------
// Host: Gauss-Legendre nodes/weights (double Newton, fixed iteration count ->
// deterministic).  Runs at capture/correctness time only; values are baked
// into the graph as kernel parameters.  No device allocation, no stream ops.
// ---------------------------------------------------------------------------
static void host_leggauss(GLTab* tab)
{
    const int n = N_NODES;
    for (int i = 0; i < n; ++i) {
        double z = cos(PI_D * ((double)i + 0.75) / ((double)n + 0.5));
        double pp = 1.0;
        for (int it = 0; it < 6; ++it) {          // fixed count: deterministic
            double p1 = z, p2 = 1.0;
            for (int j = 1; j < n; ++j) {
                double p0 = ((2.0 * j + 1.0) * z * p1 - (double)j * p2)
                            / ((double)j + 1.0);
                p2 = p1; p1 = p0;
            }
            pp = (double)n * (z * p1 - p2) / (z * z - 1.0);
            z -= p1 / pp;
        }
        tab->phi[i] = (float)tan(1.5707963267948966 * z);
        tab->wgt[i] = (float)(2.0 / ((1.0 - z * z) * pp * pp));
    }
}

// ---------------------------------------------------------------------------
// Launch
// ---------------------------------------------------------------------------
extern "C" void kernel_launch(void* const* d_in, const int* in_sizes, int n_in,
                              void* d_out, int out_size)
{
    const float* pre = (const float*)d_in[0];  // poles_re    [16,16]
    const float* pim = (const float*)d_in[1];  // poles_im    [16,16]
    const float* rre = (const float*)d_in[2];  // residues_re [16,16]
    const float* rim = (const float*)d_in[3];  // residues_im [16,16]
    float* out = (float*)d_out;                // [16,1000] float32

    GLTab tab;                                 // recomputed every call (no caching)
    host_leggauss(&tab);

    quad_kernel<<<BATCH * N_POLES * 4, 128>>>(tab, pre, pim, rre, rim);
    reduce_g0_kernel<<<80, 256>>>(pre, pim, rre, rim, out);
}